// round 3
// baseline (speedup 1.0000x reference)
#include <cuda_runtime.h>
#include <math.h>

#define EMB  512
#define H1   300
#define H2   100
#define H2P  112      // k padded to 16 threads * 7
#define NB   2
#define NPTS 256

// ---- scratch (no allocations allowed) ----
__device__ __align__(128) float g_hAa[NB*NPTS*H1];   // [b][n][h]  (+b1 folded)
__device__ __align__(128) float g_hAb[NB*NPTS*H1];   // [b][n][h]  (+b1 folded)
__device__ __align__(128) float g_hBa[NB*H1*NPTS];   // [b][h][m]
__device__ __align__(128) float g_hBb[NB*H1*NPTS];   // [b][h][m]
__device__ float g_S[NB*NPTS*4];                     // per (b,n): S0, Sx, Sy, Sz

// ============================================================================
// Kernel 1: projections  h = E^T W  (four variants), ~315M MACs
// grid (3 htiles, 32 ngroups, 8 = arr*2+b), block 128
// ============================================================================
__global__ void proj_kernel(const float* __restrict__ AE, const float* __restrict__ AnE,
                            const float* __restrict__ W1, const float* __restrict__ b1) {
    __shared__ float Es[EMB*8];
    const int tid = threadIdx.x;
    const int hx  = blockIdx.x;
    const int ng  = blockIdx.y;
    const int ab  = blockIdx.z;
    const int arr = ab >> 1;     // 0:hAa 1:hAb 2:hBa 3:hBb
    const int b   = ab & 1;
    const float* E = (arr < 2) ? AE : AnE;
    const int n0 = ng * 8;
    const float* Eb = E + (size_t)b*EMB*NPTS + n0;

    for (int i = tid; i < EMB*8; i += 128) {
        int f = i >> 3, j = i & 7;
        Es[i] = Eb[(size_t)f*NPTS + j];
    }
    __syncthreads();

    const int h = hx*128 + tid;
    if (h >= H1) return;

    const int half = arr & 1;                       // a-half -> W1[:512], b-half -> W1[512:]
    const float* Wp = W1 + (size_t)(half*EMB)*H1 + h;
    float acc[8];
    #pragma unroll
    for (int j = 0; j < 8; ++j) acc[j] = 0.f;

    #pragma unroll 4
    for (int f = 0; f < EMB; ++f) {
        const float w = Wp[(size_t)f*H1];
        const float4 e0 = *reinterpret_cast<const float4*>(&Es[f*8]);
        const float4 e1 = *reinterpret_cast<const float4*>(&Es[f*8+4]);
        acc[0] += e0.x*w; acc[1] += e0.y*w; acc[2] += e0.z*w; acc[3] += e0.w*w;
        acc[4] += e1.x*w; acc[5] += e1.y*w; acc[6] += e1.z*w; acc[7] += e1.w*w;
    }

    if (arr < 2) {
        const float bias = b1[h];
        float* out = (arr == 0 ? g_hAa : g_hAb) + ((size_t)(b*NPTS + n0))*H1 + h;
        #pragma unroll
        for (int j = 0; j < 8; ++j) out[(size_t)j*H1] = acc[j] + bias;
    } else {
        float* out = (arr == 2 ? g_hBa : g_hBb) + ((size_t)(b*H1) + h)*NPTS + n0;
        #pragma unroll
        for (int j = 0; j < 8; ++j) out[j] = acc[j];
    }
}

// ============================================================================
// Kernel 2: fused pairwise MLP + softplus + per-n reductions (dominant)
// one block per (b,n); 256 threads = 16 k-groups x 16 m-groups; micro 4m x 7k
// smem: W2 padded [300][112] + biases + sA rows + reduction pad
// ============================================================================
#define SMO_W2   0
#define SMO_B2E  (H1*H2P)           // 33600
#define SMO_W3E  (SMO_B2E + H2P)    // 33712
#define SMO_A1   (SMO_W3E + H2P)    // 33824
#define SMO_A2   (SMO_A1 + 304)     // 34128
#define SMO_RED  (SMO_A2 + 304)     // 34432  (64 x 17)
#define SMO_SS   (SMO_RED + 64*17)  // 35520
#define SM_FLOATS (SMO_SS + 8)      // 35528 -> 142112 bytes
#define SMEM2_BYTES (SM_FLOATS * 4)

__global__ void __launch_bounds__(256, 1)
pair_kernel(const float* __restrict__ W2, const float* __restrict__ b2,
            const float* __restrict__ W3, const float* __restrict__ b3,
            const float* __restrict__ AP) {
    extern __shared__ float sm[];
    const int tid = threadIdx.x;
    const int tk  = tid & 15;        // k group: columns tk*7 .. tk*7+6
    const int tm  = tid >> 4;        // m group: rows tm*4 .. tm*4+3 within 64-chunk
    const int b   = blockIdx.x >> 8;
    const int n   = blockIdx.x & 255;

    // stage W2 (zero-padded), b2/W3 (zero-padded), sA rows
    for (int i = tid; i < H1*H2P; i += 256) {
        const int h = i / H2P, k = i - h*H2P;
        sm[SMO_W2 + i] = (k < H2) ? W2[h*H2 + k] : 0.f;
    }
    if (tid < H2P) {
        sm[SMO_B2E + tid] = (tid < H2) ? b2[tid] : 0.f;
        sm[SMO_W3E + tid] = (tid < H2) ? W3[tid] : 0.f;
    }
    for (int i = tid; i < H1; i += 256) {
        sm[SMO_A1 + i] = g_hAa[((size_t)(b*NPTS + n))*H1 + i];
        sm[SMO_A2 + i] = g_hAb[((size_t)(b*NPTS + n))*H1 + i];
    }
    if (tid < 4) sm[SMO_SS + tid] = 0.f;
    __syncthreads();

    const float b3v = b3[0];
    const float* wrow = sm + SMO_W2 + tk*7;

    for (int mc = 0; mc < 4; ++mc) {
        const int mbase = mc * 64;
        float z1[4][7], z2[4][7];
        #pragma unroll
        for (int i = 0; i < 4; ++i)
            #pragma unroll
            for (int j = 0; j < 7; ++j) { z1[i][j] = 0.f; z2[i][j] = 0.f; }

        const float4* pBb = reinterpret_cast<const float4*>(
            g_hBb + (size_t)b*H1*NPTS + mbase + tm*4);
        const float4* pBa = reinterpret_cast<const float4*>(
            g_hBa + (size_t)b*H1*NPTS + mbase + tm*4);

        #pragma unroll 2
        for (int h = 0; h < H1; ++h) {
            const float a1 = sm[SMO_A1 + h];
            const float a2 = sm[SMO_A2 + h];
            const float4 vb = pBb[h*(NPTS/4)];
            const float4 va = pBa[h*(NPTS/4)];
            float w[7];
            #pragma unroll
            for (int j = 0; j < 7; ++j) w[j] = wrow[h*H2P + j];

            float r1[4], r2[4];
            r1[0] = fmaxf(a1+vb.x, 0.f); r1[1] = fmaxf(a1+vb.y, 0.f);
            r1[2] = fmaxf(a1+vb.z, 0.f); r1[3] = fmaxf(a1+vb.w, 0.f);
            r2[0] = fmaxf(a2+va.x, 0.f); r2[1] = fmaxf(a2+va.y, 0.f);
            r2[2] = fmaxf(a2+va.z, 0.f); r2[3] = fmaxf(a2+va.w, 0.f);

            #pragma unroll
            for (int i = 0; i < 4; ++i)
                #pragma unroll
                for (int j = 0; j < 7; ++j) {
                    z1[i][j] += r1[i]*w[j];
                    z2[i][j] += r2[i]*w[j];
                }
        }

        // layer 3: relu(z + b2) . W3  (padded k columns contribute exactly 0)
        #pragma unroll
        for (int i = 0; i < 4; ++i) {
            float p = 0.f;
            #pragma unroll
            for (int j = 0; j < 7; ++j) {
                const int k = tk*7 + j;
                const float bb = sm[SMO_B2E + k];
                const float ww = sm[SMO_W3E + k];
                p += fmaxf(z1[i][j] + bb, 0.f) * ww;
                p += fmaxf(z2[i][j] + bb, 0.f) * ww;
            }
            sm[SMO_RED + (tm*4 + i)*17 + tk] = p;
        }
        __syncthreads();

        if (tid < 64) {
            float x = 0.f;
            #pragma unroll
            for (int t = 0; t < 16; ++t) x += sm[SMO_RED + tid*17 + t];
            x = 0.5f*x + b3v;
            // softplus, stable: max(x,0) + log1p(exp(-|x|))
            const float R = fmaxf(x, 0.f) + log1pf(expf(-fabsf(x)));
            const int m = mbase + tid;
            const float px = AP[b*768 +       m];
            const float py = AP[b*768 + 256 + m];
            const float pz = AP[b*768 + 512 + m];
            const float dd = px*px + py*py + pz*pz - R*R;
            atomicAdd(&sm[SMO_SS+0], dd);
            atomicAdd(&sm[SMO_SS+1], dd*px);
            atomicAdd(&sm[SMO_SS+2], dd*py);
            atomicAdd(&sm[SMO_SS+3], dd*pz);
        }
        __syncthreads();
    }
    if (tid < 4) g_S[((size_t)(b*NPTS + n))*4 + tid] = sm[SMO_SS + tid];
}

// ============================================================================
// Kernel 3: multilateration solve (per batch), grid 2 x 256
// ============================================================================
__global__ void solve_kernel(const float* __restrict__ AP, const float* __restrict__ ActP,
                             float* __restrict__ out) {
    const int b = blockIdx.x;
    const int tid = threadIdx.x;
    __shared__ float sAcc[9];
    __shared__ float sFin[12];
    if (tid < 9) sAcc[tid] = 0.f;
    __syncthreads();
    {
        const float px = AP[b*768 +       tid];
        const float py = AP[b*768 + 256 + tid];
        const float pz = AP[b*768 + 512 + tid];
        atomicAdd(&sAcc[0], px);    atomicAdd(&sAcc[1], py);    atomicAdd(&sAcc[2], pz);
        atomicAdd(&sAcc[3], px*px); atomicAdd(&sAcc[4], px*py); atomicAdd(&sAcc[5], px*pz);
        atomicAdd(&sAcc[6], py*py); atomicAdd(&sAcc[7], py*pz); atomicAdd(&sAcc[8], pz*pz);
    }
    __syncthreads();
    if (tid == 0) {
        const float invM = 1.0f/(float)NPTS;
        const float cx = sAcc[0]*invM, cy = sAcc[1]*invM, cz = sAcc[2]*invM;
        const float P00 = sAcc[3]*invM, P01 = sAcc[4]*invM, P02 = sAcc[5]*invM;
        const float P11 = sAcc[6]*invM, P12 = sAcc[7]*invM, P22 = sAcc[8]*invM;
        const float H00 = -2.f*P00 + 2.f*cx*cx, H01 = -2.f*P01 + 2.f*cx*cy;
        const float H02 = -2.f*P02 + 2.f*cx*cz, H11 = -2.f*P11 + 2.f*cy*cy;
        const float H12 = -2.f*P12 + 2.f*cy*cz, H22 = -2.f*P22 + 2.f*cz*cz;
        // symmetric 3x3 inverse via cofactors
        const float A00 = H11*H22 - H12*H12;
        const float A01 = H02*H12 - H01*H22;
        const float A02 = H01*H12 - H02*H11;
        const float A11 = H00*H22 - H02*H02;
        const float A12 = H02*H01 - H00*H12;
        const float A22 = H00*H11 - H01*H01;
        const float det = H00*A00 + H01*A01 + H02*A02;
        const float id  = 1.f/det;
        const float cc  = cx*cx + cy*cy + cz*cz;
        const float t0  = P00*cx + P01*cy + P02*cz;   // PPt_mean @ c
        const float t1  = P01*cx + P11*cy + P12*cz;
        const float t2  = P02*cx + P12*cy + P22*cz;
        sFin[0] = A00*id; sFin[1] = A01*id; sFin[2] = A02*id;
        sFin[3] = A11*id; sFin[4] = A12*id; sFin[5] = A22*id;
        sFin[6] = cx; sFin[7] = cy; sFin[8] = cz;
        sFin[9]  = -2.f*t0 + 2.f*cc*cx;               // n-independent part of f
        sFin[10] = -2.f*t1 + 2.f*cc*cy;
        sFin[11] = -2.f*t2 + 2.f*cc*cz;
    }
    __syncthreads();
    const float invM = 1.0f/(float)NPTS;
    const float* S = g_S + ((size_t)(b*NPTS) + tid)*4;
    const float mwd = S[0]*invM;
    const float f0 = S[1]*invM + sFin[9]  - mwd*sFin[6];
    const float f1 = S[2]*invM + sFin[10] - mwd*sFin[7];
    const float f2 = S[3]*invM + sFin[11] - mwd*sFin[8];
    const float I00=sFin[0], I01=sFin[1], I02=sFin[2], I11=sFin[3], I12=sFin[4], I22=sFin[5];
    const float q0 = -(I00*f0 + I01*f1 + I02*f2);
    const float q1 = -(I01*f0 + I11*f1 + I12*f2);
    const float q2 = -(I02*f0 + I12*f1 + I22*f2);
    out[b*768 +       tid] = q0 + sFin[6] - ActP[b*768 +       tid];
    out[b*768 + 256 + tid] = q1 + sFin[7] - ActP[b*768 + 256 + tid];
    out[b*768 + 512 + tid] = q2 + sFin[8] - ActP[b*768 + 512 + tid];
}

// ============================================================================
extern "C" void kernel_launch(void* const* d_in, const int* in_sizes, int n_in,
                              void* d_out, int out_size) {
    const float* AE   = (const float*)d_in[0];   // action_embedding  (2,512,256)
    const float* AnE  = (const float*)d_in[1];   // anchor_embedding  (2,512,256)
    const float* ActP = (const float*)d_in[2];   // action_points     (2,3,256)
    const float* AP   = (const float*)d_in[3];   // anchor_points     (2,3,256)
    const float* W1   = (const float*)d_in[4];   // (1024,300)
    const float* b1   = (const float*)d_in[5];   // (300,)
    const float* W2   = (const float*)d_in[6];   // (300,100)
    const float* b2   = (const float*)d_in[7];   // (100,)
    const float* W3   = (const float*)d_in[8];   // (100,1)
    const float* b3   = (const float*)d_in[9];   // (1,)
    float* out = (float*)d_out;

    cudaFuncSetAttribute(pair_kernel, cudaFuncAttributeMaxDynamicSharedMemorySize,
                         SMEM2_BYTES);

    proj_kernel<<<dim3(3, 32, 8), 128>>>(AE, AnE, W1, b1);
    pair_kernel<<<dim3(NB*NPTS), 256, SMEM2_BYTES>>>(W2, b2, W3, b3, AP);
    solve_kernel<<<NB, 256>>>(AP, ActP, out);
}

// round 4
// speedup vs baseline: 1.6789x; 1.6789x over previous
#include <cuda_runtime.h>
#include <math.h>

#define EMB  512
#define H1   300
#define H2   100
#define NB   2
#define NPTS 256

typedef unsigned long long ull;

// ---- scratch (no allocations allowed) ----
__device__ __align__(128) float g_hAa[NB*NPTS*H1];          // [b][n][h] (+b1)
__device__ __align__(128) float g_hAb[NB*NPTS*H1];          // [b][n][h] (+b1)
__device__ __align__(128) float g_hBa[NB*H1*NPTS + NPTS];   // [b][h][m] (+1 row pad for prefetch)
__device__ __align__(128) float g_hBb[NB*H1*NPTS + NPTS];   // [b][h][m] (+1 row pad)
__device__ float g_S[NB*NPTS*8];                            // per (b,n,half): S0,Sx,Sy,Sz

// ---- packed fp32x2 helpers (FFMA2 path: PTX-only, ptxas won't auto-fuse) ----
__device__ __forceinline__ ull dup2(float x) {
    ull r; unsigned u = __float_as_uint(x);
    asm("mov.b64 %0, {%1, %1};" : "=l"(r) : "r"(u));
    return r;
}
__device__ __forceinline__ ull fadd2(ull a, ull b) {
    ull r; asm("add.rn.f32x2 %0, %1, %2;" : "=l"(r) : "l"(a), "l"(b)); return r;
}
__device__ __forceinline__ ull ffma2(ull a, ull b, ull c) {
    ull r; asm("fma.rn.f32x2 %0, %1, %2, %3;" : "=l"(r) : "l"(a), "l"(b), "l"(c)); return r;
}
// relu on both lanes via sign-mask (SHF+LOP3 on the otherwise-idle ALU pipe)
__device__ __forceinline__ ull relu2(ull v) {
    unsigned lo, hi;
    asm("mov.b64 {%0, %1}, %2;" : "=r"(lo), "=r"(hi) : "l"(v));
    lo &= ~(unsigned)((int)lo >> 31);
    hi &= ~(unsigned)((int)hi >> 31);
    ull r; asm("mov.b64 %0, {%1, %2};" : "=l"(r) : "r"(lo), "r"(hi));
    return r;
}
__device__ __forceinline__ float2 unpk(ull v) {
    float2 f; asm("mov.b64 {%0, %1}, %2;" : "=f"(f.x), "=f"(f.y) : "l"(v)); return f;
}

// ============================================================================
// Kernel 1: projections  h = E^T W (x4)  — prefetch w by 8 for MLP
// grid (3 htiles, 32 ngroups, 8 = arr*2+b), block 128
// ============================================================================
__global__ void proj_kernel(const float* __restrict__ AE, const float* __restrict__ AnE,
                            const float* __restrict__ W1, const float* __restrict__ b1) {
    __shared__ float Es[EMB*8];
    const int tid = threadIdx.x;
    const int hx  = blockIdx.x;
    const int ng  = blockIdx.y;
    const int ab  = blockIdx.z;
    const int arr = ab >> 1;     // 0:hAa 1:hAb 2:hBa 3:hBb
    const int b   = ab & 1;
    const float* E = (arr < 2) ? AE : AnE;
    const int n0 = ng * 8;
    const float* Eb = E + (size_t)b*EMB*NPTS + n0;

    for (int i = tid; i < EMB*8; i += 128) {
        int f = i >> 3, j = i & 7;
        Es[i] = Eb[(size_t)f*NPTS + j];
    }
    __syncthreads();

    const int h = hx*128 + tid;
    if (h >= H1) return;

    const int half = arr & 1;
    const float* Wp = W1 + (size_t)(half*EMB)*H1 + h;
    float acc[8];
    #pragma unroll
    for (int j = 0; j < 8; ++j) acc[j] = 0.f;

    #pragma unroll 1
    for (int f0 = 0; f0 < EMB; f0 += 8) {
        float wreg[8];
        #pragma unroll
        for (int t = 0; t < 8; ++t) wreg[t] = Wp[(size_t)(f0 + t)*H1];
        #pragma unroll
        for (int t = 0; t < 8; ++t) {
            const float w = wreg[t];
            const float4 e0 = *reinterpret_cast<const float4*>(&Es[(f0+t)*8]);
            const float4 e1 = *reinterpret_cast<const float4*>(&Es[(f0+t)*8+4]);
            acc[0] += e0.x*w; acc[1] += e0.y*w; acc[2] += e0.z*w; acc[3] += e0.w*w;
            acc[4] += e1.x*w; acc[5] += e1.y*w; acc[6] += e1.z*w; acc[7] += e1.w*w;
        }
    }

    if (arr < 2) {
        const float bias = b1[h];
        float* out = (arr == 0 ? g_hAa : g_hAb) + ((size_t)(b*NPTS + n0))*H1 + h;
        #pragma unroll
        for (int j = 0; j < 8; ++j) out[(size_t)j*H1] = acc[j] + bias;
    } else {
        float* out = (arr == 2 ? g_hBa : g_hBb) + ((size_t)(b*H1) + h)*NPTS + n0;
        #pragma unroll
        for (int j = 0; j < 8; ++j) out[j] = acc[j];
    }
}

// ============================================================================
// Kernel 2: persistent fused pairwise MLP (FFMA2) + softplus + reductions
// grid 152 persistent blocks, 256 threads = 16 tm (8 m each) x 16 tk (7 k each)
// unit u = (b, n, m-half-of-128); 1024 units
// ============================================================================
#define SMO_W2   0                    // 300 x 128 padded (tk*8+j)
#define SMO_B2E  (H1*128)             // 38400, 112
#define SMO_W3E  (SMO_B2E + 112)      // 38512, 112
#define SMO_A12  (SMO_W3E + 112)      // 38624, 600 interleaved (a1,a2)
#define SMO_RED  (SMO_A12 + 600)      // 39224, 128 x 17
#define SMO_WS   (SMO_RED + 128*17)   // 41400, 16
#define SM_FLOATS (SMO_WS + 16)       // 41416
#define SMEM2_BYTES (SM_FLOATS * 4)   // 165664 B

__global__ void __launch_bounds__(256, 1)
pair_kernel(const float* __restrict__ W2, const float* __restrict__ b2,
            const float* __restrict__ W3, const float* __restrict__ b3,
            const float* __restrict__ AP) {
    extern __shared__ float sm[];
    const int tid  = threadIdx.x;
    const int tk   = tid & 15;        // k group: k = tk*7 + j
    const int tm   = tid >> 4;        // m group: m = tm*8 + i
    const int lane = tid & 31;
    const int wid  = tid >> 5;

    // stage W2 padded to rows of 128 (8 cols per tk group, col 7 = 0)
    for (int i = tid; i < H1*128; i += 256) {
        const int h = i >> 7, c = i & 127, tkk = c >> 3, j = c & 7;
        const int k = tkk*7 + j;
        sm[SMO_W2 + i] = (j < 7 && k < H2) ? W2[h*H2 + k] : 0.f;
    }
    if (tid < 112) {
        sm[SMO_B2E + tid] = (tid < H2) ? b2[tid] : 0.f;
        sm[SMO_W3E + tid] = (tid < H2) ? W3[tid] : 0.f;
    }
    __syncthreads();
    const float b3v = b3[0];

    for (int u = blockIdx.x; u < NB*NPTS*2; u += gridDim.x) {
        const int b = u >> 9;
        const int n = (u >> 1) & 255;
        const int half = u & 1;
        const int mbase = half * 128;

        // stage sA interleaved (a1,a2) for LDS.64 broadcast
        for (int i = tid; i < H1; i += 256) {
            sm[SMO_A12 + 2*i]     = g_hAa[((size_t)(b*NPTS + n))*H1 + i];
            sm[SMO_A12 + 2*i + 1] = g_hAb[((size_t)(b*NPTS + n))*H1 + i];
        }
        __syncthreads();   // BAR1

        ull z1[4][7], z2[4][7];
        #pragma unroll
        for (int p = 0; p < 4; ++p)
            #pragma unroll
            for (int j = 0; j < 7; ++j) { z1[p][j] = 0ull; z2[p][j] = 0ull; }

        const ulonglong2* pBb = ((const ulonglong2*)(g_hBb + (size_t)b*H1*NPTS + mbase)) + tm*2;
        const ulonglong2* pBa = ((const ulonglong2*)(g_hBa + (size_t)b*H1*NPTS + mbase)) + tm*2;

        // software-pipelined global loads (prefetch distance 1 row; arrays padded)
        ulonglong2 nb0 = pBb[0], nb1 = pBb[1], na0 = pBa[0], na1 = pBa[1];

        #pragma unroll 1
        for (int h = 0; h < H1; ++h) {
            const ulonglong2 cb0 = nb0, cb1 = nb1, ca0 = na0, ca1 = na1;
            nb0 = pBb[(h+1)*64];  nb1 = pBb[(h+1)*64 + 1];
            na0 = pBa[(h+1)*64];  na1 = pBa[(h+1)*64 + 1];

            const float2 a = *(const float2*)(sm + SMO_A12 + 2*h);
            const ull a1d = dup2(a.x);
            const ull a2d = dup2(a.y);

            const ull r10 = relu2(fadd2(a1d, cb0.x));
            const ull r11 = relu2(fadd2(a1d, cb0.y));
            const ull r12 = relu2(fadd2(a1d, cb1.x));
            const ull r13 = relu2(fadd2(a1d, cb1.y));
            const ull r20 = relu2(fadd2(a2d, ca0.x));
            const ull r21 = relu2(fadd2(a2d, ca0.y));
            const ull r22 = relu2(fadd2(a2d, ca1.x));
            const ull r23 = relu2(fadd2(a2d, ca1.y));

            const float4 w0 = *(const float4*)(sm + SMO_W2 + h*128 + tk*8);
            const float4 w1 = *(const float4*)(sm + SMO_W2 + h*128 + tk*8 + 4);
            const float wj[7] = {w0.x, w0.y, w0.z, w0.w, w1.x, w1.y, w1.z};

            #pragma unroll
            for (int j = 0; j < 7; ++j) {
                const ull wd = dup2(wj[j]);
                z1[0][j] = ffma2(r10, wd, z1[0][j]);
                z1[1][j] = ffma2(r11, wd, z1[1][j]);
                z1[2][j] = ffma2(r12, wd, z1[2][j]);
                z1[3][j] = ffma2(r13, wd, z1[3][j]);
                z2[0][j] = ffma2(r20, wd, z2[0][j]);
                z2[1][j] = ffma2(r21, wd, z2[1][j]);
                z2[2][j] = ffma2(r22, wd, z2[2][j]);
                z2[3][j] = ffma2(r23, wd, z2[3][j]);
            }
        }

        // layer 3 per thread: relu(z + b2) . W3  (padded k -> exact 0)
        float bb[7], ww[7];
        #pragma unroll
        for (int j = 0; j < 7; ++j) {
            bb[j] = sm[SMO_B2E + tk*7 + j];
            ww[j] = sm[SMO_W3E + tk*7 + j];
        }
        #pragma unroll
        for (int pi = 0; pi < 4; ++pi) {
            float plo = 0.f, phi = 0.f;
            #pragma unroll
            for (int j = 0; j < 7; ++j) {
                const float2 u1 = unpk(z1[pi][j]);
                const float2 u2 = unpk(z2[pi][j]);
                plo += fmaxf(u1.x + bb[j], 0.f)*ww[j] + fmaxf(u2.x + bb[j], 0.f)*ww[j];
                phi += fmaxf(u1.y + bb[j], 0.f)*ww[j] + fmaxf(u2.y + bb[j], 0.f)*ww[j];
            }
            sm[SMO_RED + (tm*8 + pi*2    )*17 + tk] = plo;
            sm[SMO_RED + (tm*8 + pi*2 + 1)*17 + tk] = phi;
        }
        __syncthreads();   // BAR2

        if (tid < 128) {
            float x = 0.f;
            #pragma unroll
            for (int t = 0; t < 16; ++t) x += sm[SMO_RED + tid*17 + t];
            x = 0.5f*x + b3v;
            const float R = fmaxf(x, 0.f) + log1pf(expf(-fabsf(x)));   // softplus
            const int m = mbase + tid;
            const float px = AP[b*768 +       m];
            const float py = AP[b*768 + 256 + m];
            const float pz = AP[b*768 + 512 + m];
            float dd = px*px + py*py + pz*pz - R*R;
            float dx = dd*px, dy = dd*py, dz = dd*pz;
            #pragma unroll
            for (int o = 16; o; o >>= 1) {
                dd += __shfl_down_sync(0xffffffffu, dd, o);
                dx += __shfl_down_sync(0xffffffffu, dx, o);
                dy += __shfl_down_sync(0xffffffffu, dy, o);
                dz += __shfl_down_sync(0xffffffffu, dz, o);
            }
            if (lane == 0) {
                sm[SMO_WS + wid*4 + 0] = dd;
                sm[SMO_WS + wid*4 + 1] = dx;
                sm[SMO_WS + wid*4 + 2] = dy;
                sm[SMO_WS + wid*4 + 3] = dz;
            }
        }
        __syncthreads();   // BAR3

        if (tid < 4) {     // deterministic fixed-order final sum over 4 warps
            const float s = sm[SMO_WS + tid] + sm[SMO_WS + 4 + tid]
                          + sm[SMO_WS + 8 + tid] + sm[SMO_WS + 12 + tid];
            g_S[((size_t)(b*NPTS + n))*8 + half*4 + tid] = s;
        }
    }
}

// ============================================================================
// Kernel 3: multilateration solve (per batch), grid 2 x 256
// ============================================================================
__global__ void solve_kernel(const float* __restrict__ AP, const float* __restrict__ ActP,
                             float* __restrict__ out) {
    const int b = blockIdx.x;
    const int tid = threadIdx.x;
    __shared__ float sAcc[9];
    __shared__ float sFin[12];
    if (tid < 9) sAcc[tid] = 0.f;
    __syncthreads();
    {
        const float px = AP[b*768 +       tid];
        const float py = AP[b*768 + 256 + tid];
        const float pz = AP[b*768 + 512 + tid];
        atomicAdd(&sAcc[0], px);    atomicAdd(&sAcc[1], py);    atomicAdd(&sAcc[2], pz);
        atomicAdd(&sAcc[3], px*px); atomicAdd(&sAcc[4], px*py); atomicAdd(&sAcc[5], px*pz);
        atomicAdd(&sAcc[6], py*py); atomicAdd(&sAcc[7], py*pz); atomicAdd(&sAcc[8], pz*pz);
    }
    __syncthreads();
    if (tid == 0) {
        const float invM = 1.0f/(float)NPTS;
        const float cx = sAcc[0]*invM, cy = sAcc[1]*invM, cz = sAcc[2]*invM;
        const float P00 = sAcc[3]*invM, P01 = sAcc[4]*invM, P02 = sAcc[5]*invM;
        const float P11 = sAcc[6]*invM, P12 = sAcc[7]*invM, P22 = sAcc[8]*invM;
        const float H00 = -2.f*P00 + 2.f*cx*cx, H01 = -2.f*P01 + 2.f*cx*cy;
        const float H02 = -2.f*P02 + 2.f*cx*cz, H11 = -2.f*P11 + 2.f*cy*cy;
        const float H12 = -2.f*P12 + 2.f*cy*cz, H22 = -2.f*P22 + 2.f*cz*cz;
        const float A00 = H11*H22 - H12*H12;
        const float A01 = H02*H12 - H01*H22;
        const float A02 = H01*H12 - H02*H11;
        const float A11 = H00*H22 - H02*H02;
        const float A12 = H02*H01 - H00*H12;
        const float A22 = H00*H11 - H01*H01;
        const float det = H00*A00 + H01*A01 + H02*A02;
        const float id  = 1.f/det;
        const float cc  = cx*cx + cy*cy + cz*cz;
        const float t0  = P00*cx + P01*cy + P02*cz;
        const float t1  = P01*cx + P11*cy + P12*cz;
        const float t2  = P02*cx + P12*cy + P22*cz;
        sFin[0] = A00*id; sFin[1] = A01*id; sFin[2] = A02*id;
        sFin[3] = A11*id; sFin[4] = A12*id; sFin[5] = A22*id;
        sFin[6] = cx; sFin[7] = cy; sFin[8] = cz;
        sFin[9]  = -2.f*t0 + 2.f*cc*cx;
        sFin[10] = -2.f*t1 + 2.f*cc*cy;
        sFin[11] = -2.f*t2 + 2.f*cc*cz;
    }
    __syncthreads();
    const float invM = 1.0f/(float)NPTS;
    const float* S = g_S + ((size_t)(b*NPTS) + tid)*8;
    const float s0 = S[0] + S[4];
    const float s1 = S[1] + S[5];
    const float s2 = S[2] + S[6];
    const float s3 = S[3] + S[7];
    const float mwd = s0*invM;
    const float f0 = s1*invM + sFin[9]  - mwd*sFin[6];
    const float f1 = s2*invM + sFin[10] - mwd*sFin[7];
    const float f2 = s3*invM + sFin[11] - mwd*sFin[8];
    const float I00=sFin[0], I01=sFin[1], I02=sFin[2], I11=sFin[3], I12=sFin[4], I22=sFin[5];
    const float q0 = -(I00*f0 + I01*f1 + I02*f2);
    const float q1 = -(I01*f0 + I11*f1 + I12*f2);
    const float q2 = -(I02*f0 + I12*f1 + I22*f2);
    out[b*768 +       tid] = q0 + sFin[6] - ActP[b*768 +       tid];
    out[b*768 + 256 + tid] = q1 + sFin[7] - ActP[b*768 + 256 + tid];
    out[b*768 + 512 + tid] = q2 + sFin[8] - ActP[b*768 + 512 + tid];
}

// ============================================================================
extern "C" void kernel_launch(void* const* d_in, const int* in_sizes, int n_in,
                              void* d_out, int out_size) {
    const float* AE   = (const float*)d_in[0];   // action_embedding  (2,512,256)
    const float* AnE  = (const float*)d_in[1];   // anchor_embedding  (2,512,256)
    const float* ActP = (const float*)d_in[2];   // action_points     (2,3,256)
    const float* AP   = (const float*)d_in[3];   // anchor_points     (2,3,256)
    const float* W1   = (const float*)d_in[4];   // (1024,300)
    const float* b1   = (const float*)d_in[5];   // (300,)
    const float* W2   = (const float*)d_in[6];   // (300,100)
    const float* b2   = (const float*)d_in[7];   // (100,)
    const float* W3   = (const float*)d_in[8];   // (100,1)
    const float* b3   = (const float*)d_in[9];   // (1,)
    float* out = (float*)d_out;

    cudaFuncSetAttribute(pair_kernel, cudaFuncAttributeMaxDynamicSharedMemorySize,
                         SMEM2_BYTES);

    proj_kernel<<<dim3(3, 32, 8), 128>>>(AE, AnE, W1, b1);
    pair_kernel<<<152, 256, SMEM2_BYTES>>>(W2, b2, W3, b3, AP);
    solve_kernel<<<NB, 256>>>(AP, ActP, out);
}

// round 5
// speedup vs baseline: 1.7749x; 1.0572x over previous
#include <cuda_runtime.h>
#include <math.h>

#define EMB  512
#define H1   300
#define H2   100
#define NB   2
#define NPTS 256

typedef unsigned long long ull;

// ---- scratch (no allocations allowed) ----
__device__ __align__(128) float g_hAa[NB*NPTS*H1];          // [b][n][h] (+b1)
__device__ __align__(128) float g_hAb[NB*NPTS*H1];          // [b][n][h] (+b1)
__device__ __align__(128) float g_hBa[NB*H1*NPTS + NPTS];   // [b][h][m] (+1 row pad)
__device__ __align__(128) float g_hBb[NB*H1*NPTS + NPTS];   // [b][h][m] (+1 row pad)
__device__ float g_S[NB*NPTS*8];                            // per (b,n,half): S0,Sx,Sy,Sz

// ---- packed fp32x2 helpers ----
__device__ __forceinline__ ull dup2(float x) {
    ull r; unsigned u = __float_as_uint(x);
    asm("mov.b64 %0, {%1, %1};" : "=l"(r) : "r"(u));
    return r;
}
__device__ __forceinline__ ull ffma2(ull a, ull b, ull c) {
    ull r; asm("fma.rn.f32x2 %0, %1, %2, %3;" : "=l"(r) : "l"(a), "l"(b), "l"(c)); return r;
}
__device__ __forceinline__ float2 unpk(ull v) {
    float2 f; asm("mov.b64 {%0, %1}, %2;" : "=f"(f.x), "=f"(f.y) : "l"(v)); return f;
}

// ============================================================================
// Kernel 1: projections  h = E^T W (x4) — 16 n per block for load amortization
// grid (3 htiles, 16 ngroups, 8 = arr*2+b), block 128
// ============================================================================
__global__ void proj_kernel(const float* __restrict__ AE, const float* __restrict__ AnE,
                            const float* __restrict__ W1, const float* __restrict__ b1) {
    __shared__ float Es[EMB*16];
    const int tid = threadIdx.x;
    const int hx  = blockIdx.x;
    const int ng  = blockIdx.y;
    const int ab  = blockIdx.z;
    const int arr = ab >> 1;     // 0:hAa 1:hAb 2:hBa 3:hBb
    const int b   = ab & 1;
    const float* E = (arr < 2) ? AE : AnE;
    const int n0 = ng * 16;
    const float* Eb = E + (size_t)b*EMB*NPTS + n0;

    for (int i = tid; i < EMB*16; i += 128) {
        int f = i >> 4, j = i & 15;
        Es[i] = Eb[(size_t)f*NPTS + j];
    }
    __syncthreads();

    const int h = hx*128 + tid;
    if (h >= H1) return;

    const int half = arr & 1;
    const float* Wp = W1 + (size_t)(half*EMB)*H1 + h;
    float acc[16];
    #pragma unroll
    for (int j = 0; j < 16; ++j) acc[j] = 0.f;

    #pragma unroll 1
    for (int f0 = 0; f0 < EMB; f0 += 8) {
        float wreg[8];
        #pragma unroll
        for (int t = 0; t < 8; ++t) wreg[t] = Wp[(size_t)(f0 + t)*H1];
        #pragma unroll
        for (int t = 0; t < 8; ++t) {
            const float w = wreg[t];
            #pragma unroll
            for (int q = 0; q < 4; ++q) {
                const float4 e = *reinterpret_cast<const float4*>(&Es[(f0+t)*16 + q*4]);
                acc[q*4+0] += e.x*w; acc[q*4+1] += e.y*w;
                acc[q*4+2] += e.z*w; acc[q*4+3] += e.w*w;
            }
        }
    }

    if (arr < 2) {
        const float bias = b1[h];
        float* out = (arr == 0 ? g_hAa : g_hAb) + ((size_t)(b*NPTS + n0))*H1 + h;
        #pragma unroll
        for (int j = 0; j < 16; ++j) out[(size_t)j*H1] = acc[j] + bias;
    } else {
        float* out = (arr == 2 ? g_hBa : g_hBb) + ((size_t)(b*H1) + h)*NPTS + n0;
        #pragma unroll
        for (int j = 0; j < 16; ++j) out[j] = acc[j];
    }
}

// ============================================================================
// Kernel 2: persistent fused pairwise MLP (FFMA2, k-pair packing) + reductions
// 152 persistent blocks, 256 threads = 8 tk (7 k-pairs) x 32 tm (4 m)
// unit u = (b, n, m-half-of-128); 1024 units
// ============================================================================
#define SMO_W2   0                    // 300 rows x 128 floats (64 pair slots, swizzled)
#define SMO_B2P  (H1*128)             // 38400, 128 (64 pair slots x float2)
#define SMO_W3P  (SMO_B2P + 128)      // 38528, 128
#define SMO_A12  (SMO_W3P + 128)      // 38656, 600 interleaved (a1,a2)
#define SMO_RED  (SMO_A12 + 600)      // 39256, 128 x 9
#define SMO_WS   (SMO_RED + 128*9)    // 40408, 16
#define SM_FLOATS (SMO_WS + 16)       // 40424
#define SMEM2_BYTES (SM_FLOATS * 4)   // 161696 B

__global__ void __launch_bounds__(256, 1)
pair_kernel(const float* __restrict__ W2, const float* __restrict__ b2,
            const float* __restrict__ W3, const float* __restrict__ b3,
            const float* __restrict__ AP) {
    extern __shared__ float sm[];
    const int tid  = threadIdx.x;
    const int tk   = tid & 7;         // k group: pairs p = tk*7 + j, j=0..6  (k = 2p,2p+1)
    const int tm   = tid >> 3;        // m group: m = tm*4 + i
    const int lane = tid & 31;
    const int wid  = tid >> 5;

    // ---- stage W2 as swizzled pair rows ----
    // physical float index within row: c = g*16 + pc*4 + q*2 + e
    //   g = tk group, pc = physical 16B chunk, logical chunk jc = (pc - (g>>1)) & 3,
    //   slot j = 2*jc + q (j=7 -> zero pad), pair p = g*7 + j, k = 2p + e
    for (int i = tid; i < H1*128; i += 256) {
        const int h  = i >> 7;
        const int c  = i & 127;
        const int g  = c >> 4;
        const int pc = (c >> 2) & 3;
        const int q  = (c >> 1) & 1;
        const int e  = c & 1;
        const int jc = (pc - (g >> 1)) & 3;
        const int j  = jc*2 + q;
        const int k  = (g*7 + j)*2 + e;
        sm[SMO_W2 + i] = (j < 7 && k < H2) ? W2[h*H2 + k] : 0.f;
    }
    // b2 / W3 pair tables, slot s = g*8 + j
    if (tid < 128) {
        const int s = tid >> 1, e = tid & 1;
        const int g = s >> 3, j = s & 7;
        const int k = (g*7 + j)*2 + e;
        const float bv = (j < 7 && k < H2) ? b2[k] : 0.f;
        const float wv = (j < 7 && k < H2) ? W3[k] : 0.f;
        sm[SMO_B2P + tid] = bv;
        sm[SMO_W3P + tid] = wv;
    }
    __syncthreads();
    const float b3v = b3[0];

    for (int u = blockIdx.x; u < NB*NPTS*2; u += gridDim.x) {
        const int b = u >> 9;
        const int n = (u >> 1) & 255;
        const int half = u & 1;
        const int mbase = half * 128;

        for (int i = tid; i < H1; i += 256) {
            sm[SMO_A12 + 2*i]     = g_hAa[((size_t)(b*NPTS + n))*H1 + i];
            sm[SMO_A12 + 2*i + 1] = g_hAb[((size_t)(b*NPTS + n))*H1 + i];
        }
        __syncthreads();   // BAR1

        ull z1[4][7], z2[4][7];
        #pragma unroll
        for (int p = 0; p < 4; ++p)
            #pragma unroll
            for (int j = 0; j < 7; ++j) { z1[p][j] = 0ull; z2[p][j] = 0ull; }

        const float4* pBb = reinterpret_cast<const float4*>(
            g_hBb + (size_t)b*H1*NPTS + mbase) + tm;
        const float4* pBa = reinterpret_cast<const float4*>(
            g_hBa + (size_t)b*H1*NPTS + mbase) + tm;

        float4 nb = pBb[0], na = pBa[0];

        const float* wbase = sm + SMO_W2 + tk*16;
        const int sw0 = ((0 + (tk >> 1)) & 3) << 2;
        const int sw1 = ((1 + (tk >> 1)) & 3) << 2;
        const int sw2 = ((2 + (tk >> 1)) & 3) << 2;
        const int sw3 = ((3 + (tk >> 1)) & 3) << 2;

        #pragma unroll 1
        for (int h = 0; h < H1; ++h) {
            const float4 cb = nb, ca = na;
            nb = pBb[(h+1)*64];
            na = pBa[(h+1)*64];

            // w pairs: 4 conflict-free LDS.128 -> 8 slots (use 7)
            const float* wrow = wbase + h*128;
            const ulonglong2 w0 = *reinterpret_cast<const ulonglong2*>(wrow + sw0);
            const ulonglong2 w1 = *reinterpret_cast<const ulonglong2*>(wrow + sw1);
            const ulonglong2 w2 = *reinterpret_cast<const ulonglong2*>(wrow + sw2);
            const ulonglong2 w3 = *reinterpret_cast<const ulonglong2*>(wrow + sw3);
            const ull wp[7] = {w0.x, w0.y, w1.x, w1.y, w2.x, w2.y, w3.x};

            const float2 a = *(const float2*)(sm + SMO_A12 + 2*h);

            // scalar relu (FADD on fma pipe + FMNMX on alu pipe), then dup
            const ull d10 = dup2(fmaxf(a.x + cb.x, 0.f));
            const ull d11 = dup2(fmaxf(a.x + cb.y, 0.f));
            const ull d12 = dup2(fmaxf(a.x + cb.z, 0.f));
            const ull d13 = dup2(fmaxf(a.x + cb.w, 0.f));
            const ull d20 = dup2(fmaxf(a.y + ca.x, 0.f));
            const ull d21 = dup2(fmaxf(a.y + ca.y, 0.f));
            const ull d22 = dup2(fmaxf(a.y + ca.z, 0.f));
            const ull d23 = dup2(fmaxf(a.y + ca.w, 0.f));

            #pragma unroll
            for (int j = 0; j < 7; ++j) {
                const ull w = wp[j];
                z1[0][j] = ffma2(d10, w, z1[0][j]);
                z1[1][j] = ffma2(d11, w, z1[1][j]);
                z1[2][j] = ffma2(d12, w, z1[2][j]);
                z1[3][j] = ffma2(d13, w, z1[3][j]);
                z2[0][j] = ffma2(d20, w, z2[0][j]);
                z2[1][j] = ffma2(d21, w, z2[1][j]);
                z2[2][j] = ffma2(d22, w, z2[2][j]);
                z2[3][j] = ffma2(d23, w, z2[3][j]);
            }
        }

        // ---- layer 3: relu(z + b2) . W3  (zero-padded pairs contribute 0) ----
        float2 bb[7], ww[7];
        #pragma unroll
        for (int j = 0; j < 7; ++j) {
            bb[j] = ((const float2*)(sm + SMO_B2P))[tk*8 + j];
            ww[j] = ((const float2*)(sm + SMO_W3P))[tk*8 + j];
        }
        #pragma unroll
        for (int i = 0; i < 4; ++i) {
            float p = 0.f;
            #pragma unroll
            for (int j = 0; j < 7; ++j) {
                const float2 u1 = unpk(z1[i][j]);
                const float2 u2 = unpk(z2[i][j]);
                p += fmaxf(u1.x + bb[j].x, 0.f)*ww[j].x + fmaxf(u1.y + bb[j].y, 0.f)*ww[j].y;
                p += fmaxf(u2.x + bb[j].x, 0.f)*ww[j].x + fmaxf(u2.y + bb[j].y, 0.f)*ww[j].y;
            }
            sm[SMO_RED + (tm*4 + i)*9 + tk] = p;
        }
        __syncthreads();   // BAR2

        if (tid < 128) {
            float x = 0.f;
            #pragma unroll
            for (int t = 0; t < 8; ++t) x += sm[SMO_RED + tid*9 + t];
            x = 0.5f*x + b3v;
            const float R = fmaxf(x, 0.f) + log1pf(expf(-fabsf(x)));   // softplus
            const int m = mbase + tid;
            const float px = AP[b*768 +       m];
            const float py = AP[b*768 + 256 + m];
            const float pz = AP[b*768 + 512 + m];
            float dd = px*px + py*py + pz*pz - R*R;
            float dx = dd*px, dy = dd*py, dz = dd*pz;
            #pragma unroll
            for (int o = 16; o; o >>= 1) {
                dd += __shfl_down_sync(0xffffffffu, dd, o);
                dx += __shfl_down_sync(0xffffffffu, dx, o);
                dy += __shfl_down_sync(0xffffffffu, dy, o);
                dz += __shfl_down_sync(0xffffffffu, dz, o);
            }
            if (lane == 0) {
                sm[SMO_WS + wid*4 + 0] = dd;
                sm[SMO_WS + wid*4 + 1] = dx;
                sm[SMO_WS + wid*4 + 2] = dy;
                sm[SMO_WS + wid*4 + 3] = dz;
            }
        }
        __syncthreads();   // BAR3

        if (tid < 4) {     // deterministic fixed-order final sum over 4 warps
            const float s = sm[SMO_WS + tid] + sm[SMO_WS + 4 + tid]
                          + sm[SMO_WS + 8 + tid] + sm[SMO_WS + 12 + tid];
            g_S[((size_t)(b*NPTS + n))*8 + half*4 + tid] = s;
        }
    }
}

// ============================================================================
// Kernel 3: multilateration solve (per batch), grid 2 x 256
// ============================================================================
__global__ void solve_kernel(const float* __restrict__ AP, const float* __restrict__ ActP,
                             float* __restrict__ out) {
    const int b = blockIdx.x;
    const int tid = threadIdx.x;
    __shared__ float sAcc[9];
    __shared__ float sFin[12];
    if (tid < 9) sAcc[tid] = 0.f;
    __syncthreads();
    {
        const float px = AP[b*768 +       tid];
        const float py = AP[b*768 + 256 + tid];
        const float pz = AP[b*768 + 512 + tid];
        atomicAdd(&sAcc[0], px);    atomicAdd(&sAcc[1], py);    atomicAdd(&sAcc[2], pz);
        atomicAdd(&sAcc[3], px*px); atomicAdd(&sAcc[4], px*py); atomicAdd(&sAcc[5], px*pz);
        atomicAdd(&sAcc[6], py*py); atomicAdd(&sAcc[7], py*pz); atomicAdd(&sAcc[8], pz*pz);
    }
    __syncthreads();
    if (tid == 0) {
        const float invM = 1.0f/(float)NPTS;
        const float cx = sAcc[0]*invM, cy = sAcc[1]*invM, cz = sAcc[2]*invM;
        const float P00 = sAcc[3]*invM, P01 = sAcc[4]*invM, P02 = sAcc[5]*invM;
        const float P11 = sAcc[6]*invM, P12 = sAcc[7]*invM, P22 = sAcc[8]*invM;
        const float H00 = -2.f*P00 + 2.f*cx*cx, H01 = -2.f*P01 + 2.f*cx*cy;
        const float H02 = -2.f*P02 + 2.f*cx*cz, H11 = -2.f*P11 + 2.f*cy*cy;
        const float H12 = -2.f*P12 + 2.f*cy*cz, H22 = -2.f*P22 + 2.f*cz*cz;
        const float A00 = H11*H22 - H12*H12;
        const float A01 = H02*H12 - H01*H22;
        const float A02 = H01*H12 - H02*H11;
        const float A11 = H00*H22 - H02*H02;
        const float A12 = H02*H01 - H00*H12;
        const float A22 = H00*H11 - H01*H01;
        const float det = H00*A00 + H01*A01 + H02*A02;
        const float id  = 1.f/det;
        const float cc  = cx*cx + cy*cy + cz*cz;
        const float t0  = P00*cx + P01*cy + P02*cz;
        const float t1  = P01*cx + P11*cy + P12*cz;
        const float t2  = P02*cx + P12*cy + P22*cz;
        sFin[0] = A00*id; sFin[1] = A01*id; sFin[2] = A02*id;
        sFin[3] = A11*id; sFin[4] = A12*id; sFin[5] = A22*id;
        sFin[6] = cx; sFin[7] = cy; sFin[8] = cz;
        sFin[9]  = -2.f*t0 + 2.f*cc*cx;
        sFin[10] = -2.f*t1 + 2.f*cc*cy;
        sFin[11] = -2.f*t2 + 2.f*cc*cz;
    }
    __syncthreads();
    const float invM = 1.0f/(float)NPTS;
    const float* S = g_S + ((size_t)(b*NPTS) + tid)*8;
    const float s0 = S[0] + S[4];
    const float s1 = S[1] + S[5];
    const float s2 = S[2] + S[6];
    const float s3 = S[3] + S[7];
    const float mwd = s0*invM;
    const float f0 = s1*invM + sFin[9]  - mwd*sFin[6];
    const float f1 = s2*invM + sFin[10] - mwd*sFin[7];
    const float f2 = s3*invM + sFin[11] - mwd*sFin[8];
    const float I00=sFin[0], I01=sFin[1], I02=sFin[2], I11=sFin[3], I12=sFin[4], I22=sFin[5];
    const float q0 = -(I00*f0 + I01*f1 + I02*f2);
    const float q1 = -(I01*f0 + I11*f1 + I12*f2);
    const float q2 = -(I02*f0 + I12*f1 + I22*f2);
    out[b*768 +       tid] = q0 + sFin[6] - ActP[b*768 +       tid];
    out[b*768 + 256 + tid] = q1 + sFin[7] - ActP[b*768 + 256 + tid];
    out[b*768 + 512 + tid] = q2 + sFin[8] - ActP[b*768 + 512 + tid];
}

// ============================================================================
extern "C" void kernel_launch(void* const* d_in, const int* in_sizes, int n_in,
                              void* d_out, int out_size) {
    const float* AE   = (const float*)d_in[0];   // action_embedding  (2,512,256)
    const float* AnE  = (const float*)d_in[1];   // anchor_embedding  (2,512,256)
    const float* ActP = (const float*)d_in[2];   // action_points     (2,3,256)
    const float* AP   = (const float*)d_in[3];   // anchor_points     (2,3,256)
    const float* W1   = (const float*)d_in[4];   // (1024,300)
    const float* b1   = (const float*)d_in[5];   // (300,)
    const float* W2   = (const float*)d_in[6];   // (300,100)
    const float* b2   = (const float*)d_in[7];   // (100,)
    const float* W3   = (const float*)d_in[8];   // (100,1)
    const float* b3   = (const float*)d_in[9];   // (1,)
    float* out = (float*)d_out;

    cudaFuncSetAttribute(pair_kernel, cudaFuncAttributeMaxDynamicSharedMemorySize,
                         SMEM2_BYTES);

    proj_kernel<<<dim3(3, 16, 8), 128>>>(AE, AnE, W1, b1);
    pair_kernel<<<152, 256, SMEM2_BYTES>>>(W2, b2, W3, b3, AP);
    solve_kernel<<<NB, 256>>>(AP, ActP, out);
}

// round 7
// speedup vs baseline: 2.1056x; 1.1863x over previous
#include <cuda_runtime.h>
#include <math.h>

#define EMB  512
#define H1   300
#define H2   100
#define NB   2
#define NPTS 256

typedef unsigned long long ull;

// ---- scratch (no allocations allowed) ----
__device__ __align__(128) float g_hAa[NB*NPTS*H1];          // [b][n][h] (+b1)
__device__ __align__(128) float g_hAb[NB*NPTS*H1];          // [b][n][h] (+b1)
__device__ __align__(128) float g_hBa[NB*H1*NPTS + NPTS];   // [b][h][m] (+1 row pad)
__device__ __align__(128) float g_hBb[NB*H1*NPTS + NPTS];   // [b][h][m] (+1 row pad)
__device__ float g_S[NB*NPTS*8];                            // per (b,n,half): S0,Sx,Sy,Sz

// ---- packed fp32x2 helpers ----
__device__ __forceinline__ ull dup2(float x) {
    ull r; unsigned u = __float_as_uint(x);
    asm("mov.b64 %0, {%1, %1};" : "=l"(r) : "r"(u));
    return r;
}
__device__ __forceinline__ ull ffma2(ull a, ull b, ull c) {
    ull r; asm("fma.rn.f32x2 %0, %1, %2, %3;" : "=l"(r) : "l"(a), "l"(b), "l"(c)); return r;
}
__device__ __forceinline__ float2 unpk(ull v) {
    float2 f; asm("mov.b64 {%0, %1}, %2;" : "=f"(f.x), "=f"(f.y) : "l"(v)); return f;
}

// ============================================================================
// Kernel 1: projections  h = E^T W (x4) — 8 n per block + 8-deep w prefetch
// grid (3 htiles, 32 ngroups, 8 = arr*2+b), block 128   [measured-best config]
// ============================================================================
__global__ void proj_kernel(const float* __restrict__ AE, const float* __restrict__ AnE,
                            const float* __restrict__ W1, const float* __restrict__ b1) {
    __shared__ float Es[EMB*8];
    const int tid = threadIdx.x;
    const int hx  = blockIdx.x;
    const int ng  = blockIdx.y;
    const int ab  = blockIdx.z;
    const int arr = ab >> 1;     // 0:hAa 1:hAb 2:hBa 3:hBb
    const int b   = ab & 1;
    const float* E = (arr < 2) ? AE : AnE;
    const int n0 = ng * 8;
    const float* Eb = E + (size_t)b*EMB*NPTS + n0;

    for (int i = tid; i < EMB*8; i += 128) {
        int f = i >> 3, j = i & 7;
        Es[i] = Eb[(size_t)f*NPTS + j];
    }
    __syncthreads();

    const int h = hx*128 + tid;
    if (h >= H1) return;

    const int half = arr & 1;
    const float* Wp = W1 + (size_t)(half*EMB)*H1 + h;
    float acc[8];
    #pragma unroll
    for (int j = 0; j < 8; ++j) acc[j] = 0.f;

    #pragma unroll 1
    for (int f0 = 0; f0 < EMB; f0 += 8) {
        float wreg[8];
        #pragma unroll
        for (int t = 0; t < 8; ++t) wreg[t] = Wp[(size_t)(f0 + t)*H1];
        #pragma unroll
        for (int t = 0; t < 8; ++t) {
            const float w = wreg[t];
            const float4 e0 = *reinterpret_cast<const float4*>(&Es[(f0+t)*8]);
            const float4 e1 = *reinterpret_cast<const float4*>(&Es[(f0+t)*8+4]);
            acc[0] += e0.x*w; acc[1] += e0.y*w; acc[2] += e0.z*w; acc[3] += e0.w*w;
            acc[4] += e1.x*w; acc[5] += e1.y*w; acc[6] += e1.z*w; acc[7] += e1.w*w;
        }
    }

    if (arr < 2) {
        const float bias = b1[h];
        float* out = (arr == 0 ? g_hAa : g_hAb) + ((size_t)(b*NPTS + n0))*H1 + h;
        #pragma unroll
        for (int j = 0; j < 8; ++j) out[(size_t)j*H1] = acc[j] + bias;
    } else {
        float* out = (arr == 2 ? g_hBa : g_hBb) + ((size_t)(b*H1) + h)*NPTS + n0;
        #pragma unroll
        for (int j = 0; j < 8; ++j) out[j] = acc[j];
    }
}

// ============================================================================
// Kernel 2: persistent fused pairwise MLP (FFMA2) — 512 threads (4 warps/SMSP)
// thread tile: 2 m x 7 k-pairs x 2 branches; tk uniform per warp (broadcast w)
// unit u = (b, n, m-half-of-128); 1024 units over 152 persistent blocks
// ============================================================================
#define SMO_W2   0                    // 300 rows x 128 floats (64 pair slots)
#define SMO_B2P  (H1*128)             // 38400, 128 (64 pair slots x float2)
#define SMO_W3P  (SMO_B2P + 128)      // 38528, 128
#define SMO_A12  (SMO_W3P + 128)      // 38656, 600 interleaved (a1,a2)
#define SMO_RED  (SMO_A12 + 600)      // 39256, 128 x 9
#define SMO_WS   (SMO_RED + 128*9)    // 40408, 16
#define SM_FLOATS (SMO_WS + 16)       // 40424
#define SMEM2_BYTES (SM_FLOATS * 4)   // 161696 B

__global__ void __launch_bounds__(512, 1)
pair_kernel(const float* __restrict__ W2, const float* __restrict__ b2,
            const float* __restrict__ W3, const float* __restrict__ b3,
            const float* __restrict__ AP) {
    extern __shared__ float sm[];
    const int tid  = threadIdx.x;
    const int tk   = tid >> 6;        // 8 k groups, uniform within each warp
    const int tm   = tid & 63;        // 64 m groups, 2 m each (m = tm*2, tm*2+1)
    const int lane = tid & 31;
    const int wid  = tid >> 5;

    // ---- stage W2 as pair rows: slot s = tk*8 + j (j=0..6 used, 7 = zero pad)
    //      pair p = tk*7 + j, holds k = 2p, 2p+1
    for (int i = tid; i < H1*128; i += 512) {
        const int h = i >> 7;
        const int c = i & 127;
        const int s = c >> 1, e = c & 1;
        const int g = s >> 3, j = s & 7;
        const int k = (g*7 + j)*2 + e;
        sm[SMO_W2 + i] = (j < 7 && k < H2) ? W2[h*H2 + k] : 0.f;
    }
    if (tid < 128) {
        const int s = tid >> 1, e = tid & 1;
        const int g = s >> 3, j = s & 7;
        const int k = (g*7 + j)*2 + e;
        const bool ok = (j < 7 && k < H2);
        sm[SMO_B2P + tid] = ok ? b2[k] : 0.f;
        sm[SMO_W3P + tid] = ok ? W3[k] : 0.f;
    }
    __syncthreads();
    const float b3v = b3[0];

    for (int u = blockIdx.x; u < NB*NPTS*2; u += gridDim.x) {
        const int b = u >> 9;
        const int n = (u >> 1) & 255;
        const int half = u & 1;
        const int mbase = half * 128;

        for (int i = tid; i < H1; i += 512) {
            sm[SMO_A12 + 2*i]     = g_hAa[((size_t)(b*NPTS + n))*H1 + i];
            sm[SMO_A12 + 2*i + 1] = g_hAb[((size_t)(b*NPTS + n))*H1 + i];
        }
        __syncthreads();   // BAR1

        ull z1[2][7], z2[2][7];
        #pragma unroll
        for (int p = 0; p < 2; ++p)
            #pragma unroll
            for (int j = 0; j < 7; ++j) { z1[p][j] = 0ull; z2[p][j] = 0ull; }

        const float2* pBb = reinterpret_cast<const float2*>(
            g_hBb + (size_t)b*H1*NPTS + mbase) + tm;
        const float2* pBa = reinterpret_cast<const float2*>(
            g_hBa + (size_t)b*H1*NPTS + mbase) + tm;

        float2 nb = pBb[0], na = pBa[0];
        const float* wbase = sm + SMO_W2 + tk*16;

        #pragma unroll 2
        for (int h = 0; h < H1; ++h) {
            const float2 cb = nb, ca = na;
            nb = pBb[(h+1)*(NPTS/2)];
            na = pBa[(h+1)*(NPTS/2)];

            // warp-uniform w pair loads (broadcast, conflict-free)
            const float* wrow = wbase + h*128;
            const ulonglong2 w01 = *reinterpret_cast<const ulonglong2*>(wrow);
            const ulonglong2 w23 = *reinterpret_cast<const ulonglong2*>(wrow + 4);
            const ulonglong2 w45 = *reinterpret_cast<const ulonglong2*>(wrow + 8);
            const ulonglong2 w67 = *reinterpret_cast<const ulonglong2*>(wrow + 12);
            const ull wp[7] = {w01.x, w01.y, w23.x, w23.y, w45.x, w45.y, w67.x};

            const float2 a = *(const float2*)(sm + SMO_A12 + 2*h);

            // scalar relu (FADD fma-pipe + FMNMX alu-pipe), then dup to f32x2
            const ull d10 = dup2(fmaxf(a.x + cb.x, 0.f));
            const ull d11 = dup2(fmaxf(a.x + cb.y, 0.f));
            const ull d20 = dup2(fmaxf(a.y + ca.x, 0.f));
            const ull d21 = dup2(fmaxf(a.y + ca.y, 0.f));

            #pragma unroll
            for (int j = 0; j < 7; ++j) {
                const ull w = wp[j];
                z1[0][j] = ffma2(d10, w, z1[0][j]);
                z1[1][j] = ffma2(d11, w, z1[1][j]);
                z2[0][j] = ffma2(d20, w, z2[0][j]);
                z2[1][j] = ffma2(d21, w, z2[1][j]);
            }
        }

        // ---- layer 3: relu(z + b2) . W3  (zero-padded pairs contribute 0) ----
        float2 bb[7], ww[7];
        #pragma unroll
        for (int j = 0; j < 7; ++j) {
            bb[j] = ((const float2*)(sm + SMO_B2P))[tk*8 + j];
            ww[j] = ((const float2*)(sm + SMO_W3P))[tk*8 + j];
        }
        #pragma unroll
        for (int i = 0; i < 2; ++i) {
            float p = 0.f;
            #pragma unroll
            for (int j = 0; j < 7; ++j) {
                const float2 u1 = unpk(z1[i][j]);
                const float2 u2 = unpk(z2[i][j]);
                p += fmaxf(u1.x + bb[j].x, 0.f)*ww[j].x + fmaxf(u1.y + bb[j].y, 0.f)*ww[j].y;
                p += fmaxf(u2.x + bb[j].x, 0.f)*ww[j].x + fmaxf(u2.y + bb[j].y, 0.f)*ww[j].y;
            }
            sm[SMO_RED + (tm*2 + i)*9 + tk] = p;
        }
        __syncthreads();   // BAR2

        if (tid < 128) {
            float x = 0.f;
            #pragma unroll
            for (int t = 0; t < 8; ++t) x += sm[SMO_RED + tid*9 + t];
            x = 0.5f*x + b3v;
            const float R = fmaxf(x, 0.f) + log1pf(expf(-fabsf(x)));   // softplus
            const int m = mbase + tid;
            const float px = AP[b*768 +       m];
            const float py = AP[b*768 + 256 + m];
            const float pz = AP[b*768 + 512 + m];
            float dd = px*px + py*py + pz*pz - R*R;
            float dx = dd*px, dy = dd*py, dz = dd*pz;
            #pragma unroll
            for (int o = 16; o; o >>= 1) {
                dd += __shfl_down_sync(0xffffffffu, dd, o);
                dx += __shfl_down_sync(0xffffffffu, dx, o);
                dy += __shfl_down_sync(0xffffffffu, dy, o);
                dz += __shfl_down_sync(0xffffffffu, dz, o);
            }
            if (lane == 0) {
                sm[SMO_WS + wid*4 + 0] = dd;
                sm[SMO_WS + wid*4 + 1] = dx;
                sm[SMO_WS + wid*4 + 2] = dy;
                sm[SMO_WS + wid*4 + 3] = dz;
            }
        }
        __syncthreads();   // BAR3

        if (tid < 4) {     // deterministic fixed-order final sum over 4 warps
            const float s = sm[SMO_WS + tid] + sm[SMO_WS + 4 + tid]
                          + sm[SMO_WS + 8 + tid] + sm[SMO_WS + 12 + tid];
            g_S[((size_t)(b*NPTS + n))*8 + half*4 + tid] = s;
        }
    }
}

// ============================================================================
// Kernel 3: multilateration solve (per batch), grid 2 x 256
// ============================================================================
__global__ void solve_kernel(const float* __restrict__ AP, const float* __restrict__ ActP,
                             float* __restrict__ out) {
    const int b = blockIdx.x;
    const int tid = threadIdx.x;
    __shared__ float sAcc[9];
    __shared__ float sFin[12];
    if (tid < 9) sAcc[tid] = 0.f;
    __syncthreads();
    {
        const float px = AP[b*768 +       tid];
        const float py = AP[b*768 + 256 + tid];
        const float pz = AP[b*768 + 512 + tid];
        atomicAdd(&sAcc[0], px);    atomicAdd(&sAcc[1], py);    atomicAdd(&sAcc[2], pz);
        atomicAdd(&sAcc[3], px*px); atomicAdd(&sAcc[4], px*py); atomicAdd(&sAcc[5], px*pz);
        atomicAdd(&sAcc[6], py*py); atomicAdd(&sAcc[7], py*pz); atomicAdd(&sAcc[8], pz*pz);
    }
    __syncthreads();
    if (tid == 0) {
        const float invM = 1.0f/(float)NPTS;
        const float cx = sAcc[0]*invM, cy = sAcc[1]*invM, cz = sAcc[2]*invM;
        const float P00 = sAcc[3]*invM, P01 = sAcc[4]*invM, P02 = sAcc[5]*invM;
        const float P11 = sAcc[6]*invM, P12 = sAcc[7]*invM, P22 = sAcc[8]*invM;
        const float H00 = -2.f*P00 + 2.f*cx*cx, H01 = -2.f*P01 + 2.f*cx*cy;
        const float H02 = -2.f*P02 + 2.f*cx*cz, H11 = -2.f*P11 + 2.f*cy*cy;
        const float H12 = -2.f*P12 + 2.f*cy*cz, H22 = -2.f*P22 + 2.f*cz*cz;
        const float A00 = H11*H22 - H12*H12;
        const float A01 = H02*H12 - H01*H22;
        const float A02 = H01*H12 - H02*H11;
        const float A11 = H00*H22 - H02*H02;
        const float A12 = H02*H01 - H00*H12;
        const float A22 = H00*H11 - H01*H01;
        const float det = H00*A00 + H01*A01 + H02*A02;
        const float id  = 1.f/det;
        const float cc  = cx*cx + cy*cy + cz*cz;
        const float t0  = P00*cx + P01*cy + P02*cz;
        const float t1  = P01*cx + P11*cy + P12*cz;
        const float t2  = P02*cx + P12*cy + P22*cz;
        sFin[0] = A00*id; sFin[1] = A01*id; sFin[2] = A02*id;
        sFin[3] = A11*id; sFin[4] = A12*id; sFin[5] = A22*id;
        sFin[6] = cx; sFin[7] = cy; sFin[8] = cz;
        sFin[9]  = -2.f*t0 + 2.f*cc*cx;
        sFin[10] = -2.f*t1 + 2.f*cc*cy;
        sFin[11] = -2.f*t2 + 2.f*cc*cz;
    }
    __syncthreads();
    const float invM = 1.0f/(float)NPTS;
    const float* S = g_S + ((size_t)(b*NPTS) + tid)*8;
    const float s0 = S[0] + S[4];
    const float s1 = S[1] + S[5];
    const float s2 = S[2] + S[6];
    const float s3 = S[3] + S[7];
    const float mwd = s0*invM;
    const float f0 = s1*invM + sFin[9]  - mwd*sFin[6];
    const float f1 = s2*invM + sFin[10] - mwd*sFin[7];
    const float f2 = s3*invM + sFin[11] - mwd*sFin[8];
    const float I00=sFin[0], I01=sFin[1], I02=sFin[2], I11=sFin[3], I12=sFin[4], I22=sFin[5];
    const float q0 = -(I00*f0 + I01*f1 + I02*f2);
    const float q1 = -(I01*f0 + I11*f1 + I12*f2);
    const float q2 = -(I02*f0 + I12*f1 + I22*f2);
    out[b*768 +       tid] = q0 + sFin[6] - ActP[b*768 +       tid];
    out[b*768 + 256 + tid] = q1 + sFin[7] - ActP[b*768 + 256 + tid];
    out[b*768 + 512 + tid] = q2 + sFin[8] - ActP[b*768 + 512 + tid];
}

// ============================================================================
extern "C" void kernel_launch(void* const* d_in, const int* in_sizes, int n_in,
                              void* d_out, int out_size) {
    const float* AE   = (const float*)d_in[0];   // action_embedding  (2,512,256)
    const float* AnE  = (const float*)d_in[1];   // anchor_embedding  (2,512,256)
    const float* ActP = (const float*)d_in[2];   // action_points     (2,3,256)
    const float* AP   = (const float*)d_in[3];   // anchor_points     (2,3,256)
    const float* W1   = (const float*)d_in[4];   // (1024,300)
    const float* b1   = (const float*)d_in[5];   // (300,)
    const float* W2   = (const float*)d_in[6];   // (300,100)
    const float* b2   = (const float*)d_in[7];   // (100,)
    const float* W3   = (const float*)d_in[8];   // (100,1)
    const float* b3   = (const float*)d_in[9];   // (1,)
    float* out = (float*)d_out;

    cudaFuncSetAttribute(pair_kernel, cudaFuncAttributeMaxDynamicSharedMemorySize,
                         SMEM2_BYTES);

    proj_kernel<<<dim3(3, 32, 8), 128>>>(AE, AnE, W1, b1);
    pair_kernel<<<152, 512, SMEM2_BYTES>>>(W2, b2, W3, b3, AP);
    solve_kernel<<<NB, 256>>>(AP, ActP, out);
}

// round 14
// speedup vs baseline: 4.0200x; 1.9092x over previous
#include <cuda_runtime.h>
#include <math.h>
#include <cstdint>

#define EMB  512
#define H1   300
#define H2   100
#define NB   2
#define NPTS 256
#define KPAD 320          // h padded to 10 chunks of 32
#define PW   120          // W2T smem row stride (floats) — conflict-free B frags
#define PX   36           // X smem row stride (floats) — conflict-free A frags

// ---- scratch (no device allocations allowed) ----
__device__ __align__(128) float g_hAa[NB*NPTS*H1];    // [b][n][h] (+b1)
__device__ __align__(128) float g_hAb[NB*NPTS*H1];    // [b][n][h] (+b1)
__device__ __align__(128) float g_hBa[NB*NPTS*KPAD];  // [b][m][hpad]  (m-major)
__device__ __align__(128) float g_hBb[NB*NPTS*KPAD];  // [b][m][hpad]
__device__ float g_S[NB*NPTS*8];                      // per (b,n,mtile): S0,Sx,Sy,Sz

__device__ __forceinline__ uint32_t tf32r(float f) {   // round-to-nearest tf32
    uint32_t u; asm("cvt.rna.tf32.f32 %0, %1;" : "=r"(u) : "f"(f)); return u;
}
__device__ __forceinline__ void mma16n8k8(float* d, const uint32_t* a, const uint32_t* b) {
    asm volatile("mma.sync.aligned.m16n8k8.row.col.f32.tf32.tf32.f32 "
        "{%0,%1,%2,%3}, {%4,%5,%6,%7}, {%8,%9}, {%0,%1,%2,%3};"
        : "+f"(d[0]), "+f"(d[1]), "+f"(d[2]), "+f"(d[3])
        : "r"(a[0]), "r"(a[1]), "r"(a[2]), "r"(a[3]), "r"(b[0]), "r"(b[1]));
}

// ============================================================================
// Kernel 1: projections  h = E^T W (x4); hB stored m-major [b][m][320] + pad
// grid (3 htiles, 32 ngroups, 8 = arr*2+b), block 128
// ============================================================================
__global__ void proj_kernel(const float* __restrict__ AE, const float* __restrict__ AnE,
                            const float* __restrict__ W1, const float* __restrict__ b1) {
    __shared__ float Es[EMB*8];
    const int tid = threadIdx.x;
    const int hx  = blockIdx.x;
    const int ng  = blockIdx.y;
    const int ab  = blockIdx.z;
    const int arr = ab >> 1;     // 0:hAa 1:hAb 2:hBa 3:hBb
    const int b   = ab & 1;
    const float* E = (arr < 2) ? AE : AnE;
    const int n0 = ng * 8;
    const float* Eb = E + (size_t)b*EMB*NPTS + n0;

    for (int i = tid; i < EMB*8; i += 128) {
        int f = i >> 3, j = i & 7;
        Es[i] = Eb[(size_t)f*NPTS + j];
    }
    __syncthreads();

    const int h = hx*128 + tid;
    if (h >= H1) {
        if (arr >= 2 && h < KPAD) {   // zero-pad hB cols [300,320)
            float* out = (arr == 2 ? g_hBa : g_hBb);
            #pragma unroll
            for (int j = 0; j < 8; ++j)
                out[((size_t)(b*NPTS + n0 + j))*KPAD + h] = 0.f;
        }
        return;
    }

    const int half = arr & 1;
    const float* Wp = W1 + (size_t)(half*EMB)*H1 + h;
    float acc[8];
    #pragma unroll
    for (int j = 0; j < 8; ++j) acc[j] = 0.f;

    #pragma unroll 1
    for (int f0 = 0; f0 < EMB; f0 += 8) {
        float wreg[8];
        #pragma unroll
        for (int t = 0; t < 8; ++t) wreg[t] = Wp[(size_t)(f0 + t)*H1];
        #pragma unroll
        for (int t = 0; t < 8; ++t) {
            const float w = wreg[t];
            const float4 e0 = *reinterpret_cast<const float4*>(&Es[(f0+t)*8]);
            const float4 e1 = *reinterpret_cast<const float4*>(&Es[(f0+t)*8+4]);
            acc[0] += e0.x*w; acc[1] += e0.y*w; acc[2] += e0.z*w; acc[3] += e0.w*w;
            acc[4] += e1.x*w; acc[5] += e1.y*w; acc[6] += e1.z*w; acc[7] += e1.w*w;
        }
    }

    if (arr < 2) {
        const float bias = b1[h];
        float* out = (arr == 0 ? g_hAa : g_hAb) + ((size_t)(b*NPTS + n0))*H1 + h;
        #pragma unroll
        for (int j = 0; j < 8; ++j) out[(size_t)j*H1] = acc[j] + bias;
    } else {
        float* out = (arr == 2 ? g_hBa : g_hBb);
        #pragma unroll
        for (int j = 0; j < 8; ++j)
            out[((size_t)(b*NPTS + n0 + j))*KPAD + h] = acc[j];
    }
}

// ============================================================================
// Kernel 2: pairwise MLP via mma.sync tf32. 128 persistent CTAs x 4 units.
// 512 threads = 16 warps = 8 m-strips (16 m) x 2 n-groups (56 n); both
// branches accumulated per warp (B fragments shared). K = 320 in 10 chunks.
// ============================================================================
#define OFF_W2T  0                       // 320 x 120 tf32
#define OFF_X    (KPAD*PW)               // 38400: 2 branches x 128 x 36
#define OFF_A1   (OFF_X + 2*128*PX)      // 47616
#define OFF_A2   (OFF_A1 + KPAD)         // 47936
#define OFF_B2E  (OFF_A2 + KPAD)         // 48256 (128, zero-padded)
#define OFF_W3E  (OFF_B2E + 128)         // 48384
#define OFF_RED  (OFF_W3E + 128)         // 48512 (128 m x 2 ng)
#define OFF_WS   (OFF_RED + 256)         // 48768 (16)
#define SM_FLOATS (OFF_WS + 16)          // 48784
#define SMEM_BYTES (SM_FLOATS * 4)       // 195136 B

__global__ void __launch_bounds__(512, 1)
pair_mma(const float* __restrict__ W2, const float* __restrict__ b2,
         const float* __restrict__ W3, const float* __restrict__ b3,
         const float* __restrict__ AP) {
    extern __shared__ float sm[];
    uint32_t* smu = (uint32_t*)sm;
    const int tid   = threadIdx.x;
    const int wid   = tid >> 5;
    const int lane  = tid & 31;
    const int gid   = lane >> 2;      // 0..7
    const int tig   = lane & 3;       // 0..3
    const int strip = wid & 7;        // m-strip (16 m)
    const int ngp   = wid >> 3;       // n-group (56 n)

    // ---- stage W2^T as tf32 [k=320][n=120] (zero-padded) ----
    for (int i = tid; i < KPAD*PW; i += 512) {
        const int r = i / PW, c = i - r*PW;
        const float v = (r < H1 && c < H2) ? W2[r*H2 + c] : 0.f;
        smu[OFF_W2T + i] = tf32r(v);
    }
    if (tid < 128) {
        const bool ok = tid < H2;
        sm[OFF_B2E + tid] = ok ? b2[tid] : 0.f;
        sm[OFF_W3E + tid] = ok ? W3[tid] : 0.f;
    }
    __syncthreads();
    const float b3v = b3[0];

    for (int ui = 0; ui < 4; ++ui) {
        const int u = blockIdx.x*4 + ui;
        const int b = u >> 8;
        const int n = u & 255;

        for (int i = tid; i < KPAD; i += 512) {
            sm[OFF_A1 + i] = (i < H1) ? g_hAa[((size_t)(b*NPTS + n))*H1 + i] : 0.f;
            sm[OFF_A2 + i] = (i < H1) ? g_hAb[((size_t)(b*NPTS + n))*H1 + i] : 0.f;
        }
        __syncthreads();

        for (int mt = 0; mt < 2; ++mt) {
            float acc[2][7][4];
            #pragma unroll
            for (int br = 0; br < 2; ++br)
                #pragma unroll
                for (int t = 0; t < 7; ++t)
                    #pragma unroll
                    for (int q = 0; q < 4; ++q) acc[br][t][q] = 0.f;

            for (int kc = 0; kc < 10; ++kc) {
                __syncthreads();   // X buffers free to overwrite

                // materialize X = tf32(relu(a + hB)) for both branches
                #pragma unroll
                for (int br = 0; br < 2; ++br) {
                    const float* hB = (br == 0) ? g_hBb : g_hBa;   // v1: a1+hBb, v2: a2+hBa
                    const int aoff  = (br == 0) ? OFF_A1 : OFF_A2;
                    uint32_t* X = smu + OFF_X + br*128*PX;
                    #pragma unroll
                    for (int it = 0; it < 2; ++it) {
                        const int e  = tid + it*512;     // 0..1023
                        const int m  = e >> 3;
                        const int c4 = e & 7;
                        const float4 f4 = *(const float4*)(hB +
                            ((size_t)(b*NPTS + mt*128 + m))*KPAD + kc*32 + c4*4);
                        const float4 a4 = *(const float4*)(sm + aoff + kc*32 + c4*4);
                        uint4 v;
                        v.x = tf32r(fmaxf(a4.x + f4.x, 0.f));
                        v.y = tf32r(fmaxf(a4.y + f4.y, 0.f));
                        v.z = tf32r(fmaxf(a4.z + f4.z, 0.f));
                        v.w = tf32r(fmaxf(a4.w + f4.w, 0.f));
                        *(uint4*)(X + m*PX + c4*4) = v;
                    }
                }
                __syncthreads();

                // MMA over this 32-k chunk
                #pragma unroll
                for (int ks = 0; ks < 4; ++ks) {
                    const int krow = kc*32 + ks*8;
                    uint32_t bf[7][2];
                    const uint32_t* Wp = smu + OFF_W2T + (krow + tig)*PW + ngp*56 + gid;
                    #pragma unroll
                    for (int t = 0; t < 7; ++t) {
                        bf[t][0] = Wp[t*8];
                        bf[t][1] = Wp[t*8 + 4*PW];
                    }
                    #pragma unroll
                    for (int br = 0; br < 2; ++br) {
                        const uint32_t* X = smu + OFF_X + br*128*PX + (strip*16)*PX + ks*8;
                        uint32_t af[4];
                        af[0] = X[gid*PX + tig];
                        af[1] = X[(gid + 8)*PX + tig];
                        af[2] = X[gid*PX + tig + 4];
                        af[3] = X[(gid + 8)*PX + tig + 4];
                        #pragma unroll
                        for (int t = 0; t < 7; ++t)
                            mma16n8k8(acc[br][t], af, bf[t]);
                    }
                }
            }

            // ---- epilogue: layer-3 from D fragments ----
            // D frag: c0,c1 -> row gid, cols tig*2, tig*2+1; c2,c3 -> row gid+8
            float p0 = 0.f, p1 = 0.f;
            #pragma unroll
            for (int t = 0; t < 7; ++t) {
                const int nb = ngp*56 + t*8 + tig*2;
                const float b20 = sm[OFF_B2E + nb], b21 = sm[OFF_B2E + nb + 1];
                const float w30 = sm[OFF_W3E + nb], w31 = sm[OFF_W3E + nb + 1];
                #pragma unroll
                for (int br = 0; br < 2; ++br) {
                    p0 += fmaxf(acc[br][t][0] + b20, 0.f)*w30
                        + fmaxf(acc[br][t][1] + b21, 0.f)*w31;
                    p1 += fmaxf(acc[br][t][2] + b20, 0.f)*w30
                        + fmaxf(acc[br][t][3] + b21, 0.f)*w31;
                }
            }
            // reduce over tig (lane bits 0-1)
            p0 += __shfl_xor_sync(0xffffffffu, p0, 1);
            p0 += __shfl_xor_sync(0xffffffffu, p0, 2);
            p1 += __shfl_xor_sync(0xffffffffu, p1, 1);
            p1 += __shfl_xor_sync(0xffffffffu, p1, 2);
            if (tig == 0) {
                sm[OFF_RED + (strip*16 + gid)*2 + ngp]     = p0;
                sm[OFF_RED + (strip*16 + gid + 8)*2 + ngp] = p1;
            }
            __syncthreads();

            if (tid < 128) {
                const float x = 0.5f*(sm[OFF_RED + 2*tid] + sm[OFF_RED + 2*tid + 1]) + b3v;
                const float R = fmaxf(x, 0.f) + log1pf(expf(-fabsf(x)));   // softplus
                const int m = mt*128 + tid;
                const float px = AP[b*768 +       m];
                const float py = AP[b*768 + 256 + m];
                const float pz = AP[b*768 + 512 + m];
                float dd = px*px + py*py + pz*pz - R*R;
                float dx = dd*px, dy = dd*py, dz = dd*pz;
                #pragma unroll
                for (int o = 16; o; o >>= 1) {
                    dd += __shfl_down_sync(0xffffffffu, dd, o);
                    dx += __shfl_down_sync(0xffffffffu, dx, o);
                    dy += __shfl_down_sync(0xffffffffu, dy, o);
                    dz += __shfl_down_sync(0xffffffffu, dz, o);
                }
                if (lane == 0) {
                    sm[OFF_WS + wid*4 + 0] = dd;
                    sm[OFF_WS + wid*4 + 1] = dx;
                    sm[OFF_WS + wid*4 + 2] = dy;
                    sm[OFF_WS + wid*4 + 3] = dz;
                }
            }
            __syncthreads();
            if (tid < 4) {    // deterministic fixed-order final sum over 4 warps
                g_S[((size_t)(b*NPTS + n))*8 + mt*4 + tid] =
                    sm[OFF_WS + tid] + sm[OFF_WS + 4 + tid]
                  + sm[OFF_WS + 8 + tid] + sm[OFF_WS + 12 + tid];
            }
            __syncthreads();
        }
    }
}

// ============================================================================
// Kernel 3: multilateration solve (per batch), grid 2 x 256
// ============================================================================
__global__ void solve_kernel(const float* __restrict__ AP, const float* __restrict__ ActP,
                             float* __restrict__ out) {
    const int b = blockIdx.x;
    const int tid = threadIdx.x;
    __shared__ float sAcc[9];
    __shared__ float sFin[12];
    if (tid < 9) sAcc[tid] = 0.f;
    __syncthreads();
    {
        const float px = AP[b*768 +       tid];
        const float py = AP[b*768 + 256 + tid];
        const float pz = AP[b*768 + 512 + tid];
        atomicAdd(&sAcc[0], px);    atomicAdd(&sAcc[1], py);    atomicAdd(&sAcc[2], pz);
        atomicAdd(&sAcc[3], px*px); atomicAdd(&sAcc[4], px*py); atomicAdd(&sAcc[5], px*pz);
        atomicAdd(&sAcc[6], py*py); atomicAdd(&sAcc[7], py*pz); atomicAdd(&sAcc[8], pz*pz);
    }
    __syncthreads();
    if (tid == 0) {
        const float invM = 1.0f/(float)NPTS;
        const float cx = sAcc[0]*invM, cy = sAcc[1]*invM, cz = sAcc[2]*invM;
        const float P00 = sAcc[3]*invM, P01 = sAcc[4]*invM, P02 = sAcc[5]*invM;
        const float P11 = sAcc[6]*invM, P12 = sAcc[7]*invM, P22 = sAcc[8]*invM;
        const float H00 = -2.f*P00 + 2.f*cx*cx, H01 = -2.f*P01 + 2.f*cx*cy;
        const float H02 = -2.f*P02 + 2.f*cx*cz, H11 = -2.f*P11 + 2.f*cy*cy;
        const float H12 = -2.f*P12 + 2.f*cy*cz, H22 = -2.f*P22 + 2.f*cz*cz;
        const float A00 = H11*H22 - H12*H12;
        const float A01 = H02*H12 - H01*H22;
        const float A02 = H01*H12 - H02*H11;
        const float A11 = H00*H22 - H02*H02;
        const float A12 = H02*H01 - H00*H12;
        const float A22 = H00*H11 - H01*H01;
        const float det = H00*A00 + H01*A01 + H02*A02;
        const float id  = 1.f/det;
        const float cc  = cx*cx + cy*cy + cz*cz;
        const float t0  = P00*cx + P01*cy + P02*cz;
        const float t1  = P01*cx + P11*cy + P12*cz;
        const float t2  = P02*cx + P12*cy + P22*cz;
        sFin[0] = A00*id; sFin[1] = A01*id; sFin[2] = A02*id;
        sFin[3] = A11*id; sFin[4] = A12*id; sFin[5] = A22*id;
        sFin[6] = cx; sFin[7] = cy; sFin[8] = cz;
        sFin[9]  = -2.f*t0 + 2.f*cc*cx;
        sFin[10] = -2.f*t1 + 2.f*cc*cy;
        sFin[11] = -2.f*t2 + 2.f*cc*cz;
    }
    __syncthreads();
    const float invM = 1.0f/(float)NPTS;
    const float* S = g_S + ((size_t)(b*NPTS) + tid)*8;
    const float s0 = S[0] + S[4];
    const float s1 = S[1] + S[5];
    const float s2 = S[2] + S[6];
    const float s3 = S[3] + S[7];
    const float mwd = s0*invM;
    const float f0 = s1*invM + sFin[9]  - mwd*sFin[6];
    const float f1 = s2*invM + sFin[10] - mwd*sFin[7];
    const float f2 = s3*invM + sFin[11] - mwd*sFin[8];
    const float I00=sFin[0], I01=sFin[1], I02=sFin[2], I11=sFin[3], I12=sFin[4], I22=sFin[5];
    const float q0 = -(I00*f0 + I01*f1 + I02*f2);
    const float q1 = -(I01*f0 + I11*f1 + I12*f2);
    const float q2 = -(I02*f0 + I12*f1 + I22*f2);
    out[b*768 +       tid] = q0 + sFin[6] - ActP[b*768 +       tid];
    out[b*768 + 256 + tid] = q1 + sFin[7] - ActP[b*768 + 256 + tid];
    out[b*768 + 512 + tid] = q2 + sFin[8] - ActP[b*768 + 512 + tid];
}

// ============================================================================
extern "C" void kernel_launch(void* const* d_in, const int* in_sizes, int n_in,
                              void* d_out, int out_size) {
    const float* AE   = (const float*)d_in[0];   // action_embedding  (2,512,256)
    const float* AnE  = (const float*)d_in[1];   // anchor_embedding  (2,512,256)
    const float* ActP = (const float*)d_in[2];   // action_points     (2,3,256)
    const float* AP   = (const float*)d_in[3];   // anchor_points     (2,3,256)
    const float* W1   = (const float*)d_in[4];   // (1024,300)
    const float* b1   = (const float*)d_in[5];   // (300,)
    const float* W2   = (const float*)d_in[6];   // (300,100)
    const float* b2   = (const float*)d_in[7];   // (100,)
    const float* W3   = (const float*)d_in[8];   // (100,1)
    const float* b3   = (const float*)d_in[9];   // (1,)
    float* out = (float*)d_out;

    cudaFuncSetAttribute(pair_mma, cudaFuncAttributeMaxDynamicSharedMemorySize, SMEM_BYTES);

    proj_kernel<<<dim3(3, 32, 8), 128>>>(AE, AnE, W1, b1);
    pair_mma<<<128, 512, SMEM_BYTES>>>(W2, b2, W3, b3, AP);
    solve_kernel<<<NB, 256>>>(AP, ActP, out);
}